// round 15
// baseline (speedup 1.0000x reference)
#include <cuda_runtime.h>
#include <cuda_bf16.h>
#include <cuda_fp16.h>
#include <math.h>
#include <stdint.h>

#define BETA_C 2.35f

// ---------------- scratch (device globals; allocation-free) ----------------
__device__ float g_S[8 * 1024 * 2048];   // scores (fp32, pre-softmax)

// fp16 operands
__device__ __align__(256) __half g_qf   [8192  * 768];      // query fp16
__device__ __align__(256) __half g_cxf  [16384 * 768];      // context fp16
__device__ __align__(256) __half g_wqf  [768  * 768];
__device__ __align__(256) __half g_wkf  [1536 * 768];
__device__ __align__(256) __half g_wvf  [1536 * 768];
__device__ __align__(256) __half g_wof  [768  * 768];
__device__ __align__(256) __half g_Qf   [8192 * 768];       // Q fp16
__device__ __align__(256) __half g_Q2f  [8192 * 768];       // Q^2 fp16
__device__ __align__(256) __half g_Kmu16[16384 * 768];      // K_mu raw fp16 (pre-LN)
__device__ __align__(256) __half g_Kvf  [16384 * 768];      // softplus K var fp16
__device__ __align__(256) __half g_Kmf  [16384 * 768];      // LN(K_mu) fp16
__device__ __align__(256) __half g_Vmu16[16384 * 768];      // V_mu raw fp16 (pre-LN)
__device__ __align__(256) __half g_Vv16 [16384 * 768];      // softplus V var fp16
__device__ __align__(256) __half g_At   [8 * 1024 * 2048];  // attn fp16
__device__ __align__(256) __half g_Vt   [8 * 768 * 2048];   // V_sample^T fp16
__device__ __align__(256) __half g_Oa   [8192 * 768];       // attn@V fp16

__device__ __forceinline__ float softplus_eps(float x) {
    return (x > 20.f ? x : log1pf(expf(x))) + 1e-6f;
}
__device__ __forceinline__ uint32_t smem_u32(const void* p) {
    uint32_t a;
    asm("{ .reg .u64 t; cvta.to.shared.u64 t, %1; cvt.u32.u64 %0, t; }" : "=r"(a) : "l"(p));
    return a;
}
#define CP_COMMIT() asm volatile("cp.async.commit_group;" ::: "memory")
#define CP_WAIT2()  asm volatile("cp.async.wait_group 2;" ::: "memory")
#define CP_WAIT1()  asm volatile("cp.async.wait_group 1;" ::: "memory")
#define CP_WAIT0()  asm volatile("cp.async.wait_group 0;" ::: "memory")

__device__ __forceinline__ uint32_t swz128(uint32_t o) { return o ^ ((o >> 3) & 0x70u); }

__device__ __forceinline__ void ldsm_x4(uint32_t addr, uint32_t& r0, uint32_t& r1,
                                        uint32_t& r2, uint32_t& r3) {
    asm volatile("ldmatrix.sync.aligned.m8n8.x4.shared.b16 {%0,%1,%2,%3}, [%4];"
                 : "=r"(r0), "=r"(r1), "=r"(r2), "=r"(r3) : "r"(addr));
}
__device__ __forceinline__ void mma_f16(float* c, const uint32_t* a, const uint32_t* b) {
    asm volatile(
        "mma.sync.aligned.m16n8k16.row.col.f32.f16.f16.f32 "
        "{%0,%1,%2,%3}, {%4,%5,%6,%7}, {%8,%9}, {%0,%1,%2,%3};"
        : "+f"(c[0]), "+f"(c[1]), "+f"(c[2]), "+f"(c[3])
        : "r"(a[0]), "r"(a[1]), "r"(a[2]), "r"(a[3]), "r"(b[0]), "r"(b[1]));
}
__device__ __forceinline__ uint32_t pack_f16(float v0, float v1) {
    __half2 h = __floats2half2_rn(v0, v1);
    return *(uint32_t*)&h;
}

// =====================================================================
// fp32 -> fp16 converter
// =====================================================================
__global__ __launch_bounds__(256) void tohalf(const float* __restrict__ x,
                                              __half* __restrict__ y, int n4)
{
    int i = blockIdx.x * 256 + threadIdx.x;
    if (i >= n4) return;
    float4 v = ((const float4*)x)[i];
    ((uint2*)y)[i] = make_uint2(pack_f16(v.x, v.y), pack_f16(v.z, v.w));
}

// =====================================================================
// fp16 HMMA core: one 64-K chunk, A tile @abase, B tile @bbase (SW128)
// =====================================================================
__device__ __forceinline__ void mma_compute_1pass(
    float acc[2][4][4], uint32_t abase, uint32_t bbase, int wm, int wn, int lane)
{
    const int arow  = lane & 15;
    const int khalf = lane >> 4;
#pragma unroll
    for (int ks = 0; ks < 4; ks++) {
        const uint32_t kb = ks * 32 + khalf * 16;
        uint32_t Ah[2][4], Bh[4][2];
#pragma unroll
        for (int mi = 0; mi < 2; mi++) {
            uint32_t r = (uint32_t)((wm * 32 + mi * 16 + arow) * 128) + kb;
            ldsm_x4(abase + swz128(r), Ah[mi][0], Ah[mi][1], Ah[mi][2], Ah[mi][3]);
        }
#pragma unroll
        for (int nf = 0; nf < 2; nf++) {
            uint32_t r = (uint32_t)((wn * 32 + nf * 16 + arow) * 128) + kb;
            uint32_t r0, r1, r2, r3;
            ldsm_x4(bbase + swz128(r), r0, r1, r2, r3);
            Bh[nf * 2 + 0][0] = r0; Bh[nf * 2 + 0][1] = r2;
            Bh[nf * 2 + 1][0] = r1; Bh[nf * 2 + 1][1] = r3;
        }
#pragma unroll
        for (int mi = 0; mi < 2; mi++)
#pragma unroll
            for (int ni = 0; ni < 4; ni++)
                mma_f16(acc[mi][ni], Ah[mi], Bh[ni]);
    }
}

// tile loader: 128 rows x 64 x 16-bit (128B) from k-major gmem, SW128 swizzle
__device__ __forceinline__ void load_tile(uint32_t sdst, const uint16_t* __restrict__ src,
                                          size_t row0, int ldK, int k0, int tid)
{
#pragma unroll
    for (int i = 0; i < 2; i++) {
        int seg = tid + (i << 9);
        int row = seg >> 3;
        int sc  = seg & 7;
        const void* g = (const void*)(src + (row0 + row) * (size_t)ldK + k0 + sc * 8);
        uint32_t off = swz128((uint32_t)(row * 128 + sc * 16));
        asm volatile("cp.async.cg.shared.global [%0], [%1], 16;" :: "r"(sdst + off), "l"(g));
    }
}

#define P1_SMEM 131072
#define SC_SMEM 196608
#define LN_SMEM 61440

// =====================================================================
// 1-pass fp16 NT GEMM: C[M,N] = A[M,K] x B[N,K]^T
// 4 smem buffers, lookahead 3, one __syncthreads per chunk.
// mode 0: KV proj (N=1536) -> oh = mu fp16 (col<768); oh2 = softplus var fp16
// mode 2: AV (batched)     -> oh = fp16 (no bias)
// mode 3: O proj           -> f0 = g*(acc+bias)+(1-g)*query fp32
// mode 4: Q proj           -> oh = Q fp16; oh2 = Q^2 fp16 (bias)
// =====================================================================
__global__ __launch_bounds__(512, 1) void mma_nt_1p(
    const __half* __restrict__ A, const __half* __restrict__ B,
    int K, int mode,
    size_t sAb, size_t sBb, size_t sCb,
    const float* __restrict__ bias,
    float* __restrict__ f0,
    __half* __restrict__ oh, __half* __restrict__ oh2,
    const float* __restrict__ query, const float* __restrict__ gate)
{
    extern __shared__ char smem[];
    const uint32_t sb = smem_u32(smem);
    const int tid  = threadIdx.x;
    const int wid  = tid >> 5;
    const int lane = tid & 31;
    const int wm = wid >> 2;
    const int wn = wid & 3;
    const int z  = blockIdx.z;

    const uint16_t* pA = (const uint16_t*)A + (size_t)z * sAb;
    const uint16_t* pB = (const uint16_t*)B + (size_t)z * sBb;
    const size_t arow0 = (size_t)blockIdx.y * 128;
    const size_t brow0 = (size_t)blockIdx.x * 128;

    float acc[2][4][4];
#pragma unroll
    for (int mi = 0; mi < 2; mi++)
#pragma unroll
        for (int ni = 0; ni < 4; ni++)
#pragma unroll
            for (int r = 0; r < 4; r++) acc[mi][ni][r] = 0.f;

    const int nc = K >> 6;   // always >= 12
#pragma unroll
    for (int p = 0; p < 3; p++) {
        uint32_t buf = sb + (uint32_t)p * 32768u;
        load_tile(buf,         pA, arow0, K, p * 64, tid);
        load_tile(buf + 16384, pB, brow0, K, p * 64, tid);
        CP_COMMIT();
    }

    for (int c = 0; c < nc; c++) {
        if (c < nc - 2)      { CP_WAIT2(); }
        else if (c < nc - 1) { CP_WAIT1(); }
        else                 { CP_WAIT0(); }
        __syncthreads();
        uint32_t buf = sb + (uint32_t)(c & 3) * 32768u;
        mma_compute_1pass(acc, buf, buf + 16384, wm, wn, lane);
        if (c + 3 < nc) {
            uint32_t lb = sb + (uint32_t)((c + 3) & 3) * 32768u;
            load_tile(lb,         pA, arow0, K, (c + 3) * 64, tid);
            load_tile(lb + 16384, pB, brow0, K, (c + 3) * 64, tid);
            CP_COMMIT();
        }
    }

    float gg = 0.f, og = 0.f;
    if (mode == 3) { gg = 1.f / (1.f + expf(-gate[0])); og = 1.f - gg; }

#pragma unroll
    for (int mi = 0; mi < 2; mi++) {
#pragma unroll
        for (int ni = 0; ni < 4; ni++) {
            size_t row = (size_t)blockIdx.y * 128 + wm * 32 + mi * 16 + (lane >> 2);
            int col = blockIdx.x * 128 + wn * 32 + ni * 8 + (lane & 3) * 2;
#pragma unroll
            for (int h = 0; h < 2; h++) {
                size_t r = row + h * 8;
                float v0 = acc[mi][ni][2 * h + 0];
                float v1 = acc[mi][ni][2 * h + 1];
                if (mode == 0) {
                    v0 += bias[col]; v1 += bias[col + 1];
                    if (col < 768) {
                        *(uint32_t*)(oh + r * 768 + col) = pack_f16(v0, v1);
                    } else {
                        *(uint32_t*)(oh2 + r * 768 + (col - 768)) =
                            pack_f16(softplus_eps(v0), softplus_eps(v1));
                    }
                } else if (mode == 2) {
                    *(uint32_t*)(oh + (size_t)z * sCb + r * 768 + col) = pack_f16(v0, v1);
                } else if (mode == 3) {
                    size_t idx = r * 768 + col;
                    float2 qv = *(const float2*)(query + idx);
                    float2 o;
                    o.x = gg * (v0 + bias[col])     + og * qv.x;
                    o.y = gg * (v1 + bias[col + 1]) + og * qv.y;
                    *(float2*)(f0 + idx) = o;
                } else {  // mode 4: Q proj
                    v0 += bias[col]; v1 += bias[col + 1];
                    size_t idx = r * 768 + col;
                    *(uint32_t*)(oh  + idx) = pack_f16(v0, v1);
                    *(uint32_t*)(oh2 + idx) = pack_f16(v0 * v0, v1 * v1);
                }
            }
        }
    }
}

// =====================================================================
// Fused LN + V-sample + transpose. 32 rows/block, 8 warps (4 rows/warp).
// Kmf <- fp16(LN(Kmu16)); Vt[b,c,k] <- fp16(LN(Vmu16)+sqrt(Vv16)*eps) transposed.
// =====================================================================
__global__ __launch_bounds__(256) void ln_fuse_t(
    const float* __restrict__ kg, const float* __restrict__ kb,
    const float* __restrict__ vg, const float* __restrict__ vb,
    const float* __restrict__ eps)
{
    extern __shared__ char smraw[];
    __half (*tile)[768] = (__half(*)[768])smraw;             // 49152 B
    float* pkg = (float*)(smraw + 49152);
    float* pkb = pkg + 768;
    float* pvg = pkb + 768;
    float* pvb = pvg + 768;

    const int tid  = threadIdx.x;
    const int wid  = tid >> 5;
    const int lane = tid & 31;
    const size_t row0 = (size_t)blockIdx.x * 32;

    for (int i = tid; i < 768; i += 256) {
        pkg[i] = kg[i]; pkb[i] = kb[i]; pvg[i] = vg[i]; pvb[i] = vb[i];
    }
    __syncthreads();

#pragma unroll
    for (int rr = 0; rr < 4; rr++) {
        const int rl = wid * 4 + rr;
        const size_t base = (row0 + rl) * 768;

        // ---- K LN ----
        float x[24];
        float s = 0.f, q = 0.f;
#pragma unroll
        for (int i = 0; i < 24; i++) {
            x[i] = __half2float(g_Kmu16[base + i * 32 + lane]);
            s += x[i];
            q = fmaf(x[i], x[i], q);
        }
#pragma unroll
        for (int o = 16; o > 0; o >>= 1) {
            s += __shfl_xor_sync(0xffffffffu, s, o);
            q += __shfl_xor_sync(0xffffffffu, q, o);
        }
        float m    = s * (1.f / 768.f);
        float var  = q * (1.f / 768.f) - m * m;
        float rstd = rsqrtf(var + 1e-5f);
#pragma unroll
        for (int i = 0; i < 24; i++) {
            int c = i * 32 + lane;
            g_Kmf[base + c] = __float2half_rn((x[i] - m) * rstd * pkg[c] + pkb[c]);
        }

        // ---- V LN + sample (into smem tile) ----
        s = 0.f; q = 0.f;
#pragma unroll
        for (int i = 0; i < 24; i++) {
            x[i] = __half2float(g_Vmu16[base + i * 32 + lane]);
            s += x[i];
            q = fmaf(x[i], x[i], q);
        }
#pragma unroll
        for (int o = 16; o > 0; o >>= 1) {
            s += __shfl_xor_sync(0xffffffffu, s, o);
            q += __shfl_xor_sync(0xffffffffu, q, o);
        }
        m    = s * (1.f / 768.f);
        var  = q * (1.f / 768.f) - m * m;
        rstd = rsqrtf(var + 1e-5f);
#pragma unroll
        for (int i = 0; i < 24; i++) {
            int c = i * 32 + lane;
            float v = (x[i] - m) * rstd * pvg[c] + pvb[c]
                    + sqrtf(__half2float(g_Vv16[base + c])) * eps[base + c];
            tile[rl][c] = __float2half_rn(v);
        }
    }
    __syncthreads();

    // transposed write: each thread owns 3 columns, writes 32 contiguous halves
    const int batch = (int)(row0 >> 11);
    const int k0    = (int)(row0 & 2047);
#pragma unroll
    for (int j = 0; j < 3; j++) {
        int c = tid + j * 256;
        __half vals[32];
#pragma unroll
        for (int r = 0; r < 32; r++) vals[r] = tile[r][c];
        uint4* dst = (uint4*)(g_Vt + ((size_t)batch * 768 + c) * 2048 + k0);
        const uint4* src = (const uint4*)vals;
        dst[0] = src[0]; dst[1] = src[1]; dst[2] = src[2]; dst[3] = src[3];
    }
}

// =====================================================================
// Scores, all 1-pass fp16 (dual accumulator), 3 buffers, 1 sync/chunk:
// S[b,q,k] = (Q.Kmu)/sqrt(C) - BETA*sqrt((Q^2 . Kvar)/C)
// chunk group = 4 tiles {Qf, Kmf, Q2f, Kvf} = 64KB
// =====================================================================
__global__ __launch_bounds__(512, 1) void scores_mma(
    const __half* __restrict__ qf,  const __half* __restrict__ q2f,
    const __half* __restrict__ kmf, const __half* __restrict__ kvf,
    float* __restrict__ S)
{
    extern __shared__ char smem[];
    const uint32_t sb = smem_u32(smem);
    const int tid  = threadIdx.x;
    const int wid  = tid >> 5;
    const int lane = tid & 31;
    const int wm = wid >> 2;
    const int wn = wid & 3;
    const int b  = blockIdx.z;
    const int mt = blockIdx.y;
    const int nt = blockIdx.x;
    const size_t qrow0 = (size_t)b * 1024 + (size_t)mt * 128;
    const size_t krow0 = (size_t)b * 2048 + (size_t)nt * 128;

    float accM[2][4][4], accV[2][4][4];
#pragma unroll
    for (int mi = 0; mi < 2; mi++)
#pragma unroll
        for (int ni = 0; ni < 4; ni++)
#pragma unroll
            for (int r = 0; r < 4; r++) { accM[mi][ni][r] = 0.f; accV[mi][ni][r] = 0.f; }

    const uint16_t* pq  = (const uint16_t*)qf;
    const uint16_t* pq2 = (const uint16_t*)q2f;
    const uint16_t* pkm = (const uint16_t*)kmf;
    const uint16_t* pkv = (const uint16_t*)kvf;

#pragma unroll
    for (int p = 0; p < 2; p++) {
        uint32_t buf = sb + (uint32_t)p * 65536u;
        load_tile(buf,         pq,  qrow0, 768, p * 64, tid);
        load_tile(buf + 16384, pkm, krow0, 768, p * 64, tid);
        load_tile(buf + 32768, pq2, qrow0, 768, p * 64, tid);
        load_tile(buf + 49152, pkv, krow0, 768, p * 64, tid);
        CP_COMMIT();
    }

    uint32_t bufsel[3] = {sb, sb + 65536u, sb + 131072u};
    for (int c = 0; c < 12; c++) {
        if (c < 11) { CP_WAIT1(); } else { CP_WAIT0(); }
        __syncthreads();
        uint32_t buf = bufsel[c % 3];
        mma_compute_1pass(accM, buf,         buf + 16384, wm, wn, lane);
        mma_compute_1pass(accV, buf + 32768, buf + 49152, wm, wn, lane);
        if (c + 2 < 12) {
            uint32_t lb = bufsel[(c + 2) % 3];
            load_tile(lb,         pq,  qrow0, 768, (c + 2) * 64, tid);
            load_tile(lb + 16384, pkm, krow0, 768, (c + 2) * 64, tid);
            load_tile(lb + 32768, pq2, qrow0, 768, (c + 2) * 64, tid);
            load_tile(lb + 49152, pkv, krow0, 768, (c + 2) * 64, tid);
            CP_COMMIT();
        }
    }

    const float inv_scale = 0.03608439182435161f;  // 1/sqrt(768)
    const float invC = 1.0f / 768.0f;
    float* Sbase = S + (qrow0 * 2048) + (size_t)nt * 128;
#pragma unroll
    for (int mi = 0; mi < 2; mi++) {
#pragma unroll
        for (int ni = 0; ni < 4; ni++) {
            int col = wn * 32 + ni * 8 + (lane & 3) * 2;
            int row0 = wm * 32 + mi * 16 + (lane >> 2);
            float2 v0, v1;
            v0.x = accM[mi][ni][0] * inv_scale - BETA_C * sqrtf(accV[mi][ni][0] * invC);
            v0.y = accM[mi][ni][1] * inv_scale - BETA_C * sqrtf(accV[mi][ni][1] * invC);
            v1.x = accM[mi][ni][2] * inv_scale - BETA_C * sqrtf(accV[mi][ni][2] * invC);
            v1.y = accM[mi][ni][3] * inv_scale - BETA_C * sqrtf(accV[mi][ni][3] * invC);
            *(float2*)(Sbase + (size_t)row0 * 2048 + col)       = v0;
            *(float2*)(Sbase + (size_t)(row0 + 8) * 2048 + col) = v1;
        }
    }
}

// =====================================================================
// Row softmax over 2048 -> attn fp16
// =====================================================================
__global__ __launch_bounds__(256) void softmax_rows(
    const float* __restrict__ S, __half* __restrict__ At)
{
    const size_t row = blockIdx.x;
    const float* r = S + row * 2048;
    const int tid = threadIdx.x;
    __shared__ float sh[8];

    float4 v0 = *(const float4*)(r + tid * 4);
    float4 v1 = *(const float4*)(r + 1024 + tid * 4);

    float mx = fmaxf(fmaxf(fmaxf(v0.x, v0.y), fmaxf(v0.z, v0.w)),
                     fmaxf(fmaxf(v1.x, v1.y), fmaxf(v1.z, v1.w)));
#pragma unroll
    for (int o = 16; o > 0; o >>= 1) mx = fmaxf(mx, __shfl_xor_sync(0xffffffffu, mx, o));
    if ((tid & 31) == 0) sh[tid >> 5] = mx;
    __syncthreads();
    mx = sh[0];
#pragma unroll
    for (int i = 1; i < 8; i++) mx = fmaxf(mx, sh[i]);
    __syncthreads();

    v0.x = expf(v0.x - mx); v0.y = expf(v0.y - mx); v0.z = expf(v0.z - mx); v0.w = expf(v0.w - mx);
    v1.x = expf(v1.x - mx); v1.y = expf(v1.y - mx); v1.z = expf(v1.z - mx); v1.w = expf(v1.w - mx);
    float sum = (v0.x + v0.y + v0.z + v0.w) + (v1.x + v1.y + v1.z + v1.w);
#pragma unroll
    for (int o = 16; o > 0; o >>= 1) sum += __shfl_xor_sync(0xffffffffu, sum, o);
    if ((tid & 31) == 0) sh[tid >> 5] = sum;
    __syncthreads();
    float tot = 0.f;
#pragma unroll
    for (int i = 0; i < 8; i++) tot += sh[i];
    float inv = 1.f / tot;

    size_t i0 = row * 2048 + tid * 4;
    size_t i1 = i0 + 1024;
    *(uint32_t*)(At + i0)     = pack_f16(v0.x * inv, v0.y * inv);
    *(uint32_t*)(At + i0 + 2) = pack_f16(v0.z * inv, v0.w * inv);
    *(uint32_t*)(At + i1)     = pack_f16(v1.x * inv, v1.y * inv);
    *(uint32_t*)(At + i1 + 2) = pack_f16(v1.z * inv, v1.w * inv);
}

// =====================================================================
extern "C" void kernel_launch(void* const* d_in, const int* in_sizes, int n_in,
                              void* d_out, int out_size)
{
    const float* query     = (const float*)d_in[0];
    const float* context   = (const float*)d_in[1];
    const float* eps_noise = (const float*)d_in[2];
    const float* Wq        = (const float*)d_in[3];
    const float* bq        = (const float*)d_in[4];
    const float* Wk        = (const float*)d_in[5];
    const float* bk        = (const float*)d_in[6];
    const float* Wv        = (const float*)d_in[7];
    const float* bv        = (const float*)d_in[8];
    const float* Wo        = (const float*)d_in[9];
    const float* bo        = (const float*)d_in[10];
    const float* ln_k_g    = (const float*)d_in[11];
    const float* ln_k_b    = (const float*)d_in[12];
    const float* ln_v_g    = (const float*)d_in[13];
    const float* ln_v_b    = (const float*)d_in[14];
    const float* gate      = (const float*)d_in[15];
    float* out = (float*)d_out;

    float* pS;
    cudaGetSymbolAddress((void**)&pS, g_S);

    __half *pqf, *pcxf, *pwqf, *pwkf, *pwvf, *pwof;
    __half *pQf, *pQ2f, *pKmu16, *pKvf, *pKmf, *pVmu16, *pVv16, *pAt, *pVt, *pOa;
    cudaGetSymbolAddress((void**)&pqf,    g_qf);
    cudaGetSymbolAddress((void**)&pcxf,   g_cxf);
    cudaGetSymbolAddress((void**)&pwqf,   g_wqf);
    cudaGetSymbolAddress((void**)&pwkf,   g_wkf);
    cudaGetSymbolAddress((void**)&pwvf,   g_wvf);
    cudaGetSymbolAddress((void**)&pwof,   g_wof);
    cudaGetSymbolAddress((void**)&pQf,    g_Qf);
    cudaGetSymbolAddress((void**)&pQ2f,   g_Q2f);
    cudaGetSymbolAddress((void**)&pKmu16, g_Kmu16);
    cudaGetSymbolAddress((void**)&pKvf,   g_Kvf);
    cudaGetSymbolAddress((void**)&pKmf,   g_Kmf);
    cudaGetSymbolAddress((void**)&pVmu16, g_Vmu16);
    cudaGetSymbolAddress((void**)&pVv16,  g_Vv16);
    cudaGetSymbolAddress((void**)&pAt,    g_At);
    cudaGetSymbolAddress((void**)&pVt,    g_Vt);
    cudaGetSymbolAddress((void**)&pOa,    g_Oa);

    static int cfg_done = 0;
    if (!cfg_done) {
        cudaFuncSetAttribute(scores_mma, cudaFuncAttributeMaxDynamicSharedMemorySize, SC_SMEM);
        cudaFuncSetAttribute(mma_nt_1p,  cudaFuncAttributeMaxDynamicSharedMemorySize, P1_SMEM);
        cudaFuncSetAttribute(ln_fuse_t,  cudaFuncAttributeMaxDynamicSharedMemorySize, LN_SMEM);
        cfg_done = 1;
    }

    // 0. operand conversions (all fp16)
    tohalf<<<6144,  256>>>(query,   pqf,  6291456 / 4);
    tohalf<<<12288, 256>>>(context, pcxf, 12582912 / 4);
    tohalf<<<576,   256>>>(Wq, pwqf, 589824 / 4);
    tohalf<<<1152,  256>>>(Wk, pwkf, 1179648 / 4);
    tohalf<<<1152,  256>>>(Wv, pwvf, 1179648 / 4);
    tohalf<<<576,   256>>>(Wo, pwof, 589824 / 4);

    // 1. Q projection (mode 4) -> Qf, Q2f fp16
    mma_nt_1p<<<dim3(6, 64), 512, P1_SMEM>>>(pqf, pwqf, 768, 4,
        0, 0, 0, bq, nullptr, pQf, pQ2f, nullptr, nullptr);
    // 2. K projection (mode 0, N=1536) -> Kmu16 fp16 / Kvf fp16
    mma_nt_1p<<<dim3(12, 128), 512, P1_SMEM>>>(pcxf, pwkf, 768, 0,
        0, 0, 0, bk, nullptr, pKmu16, pKvf, nullptr, nullptr);
    // 3. V projection (mode 0, N=1536) -> Vmu16 fp16 / Vv16 fp16
    mma_nt_1p<<<dim3(12, 128), 512, P1_SMEM>>>(pcxf, pwvf, 768, 0,
        0, 0, 0, bv, nullptr, pVmu16, pVv16, nullptr, nullptr);
    // 4. fused LN + V sampling + transpose -> Kmf fp16, Vt fp16
    ln_fuse_t<<<512, 256, LN_SMEM>>>(ln_k_g, ln_k_b, ln_v_g, ln_v_b, eps_noise);
    // 5. scores (all 1-pass fp16, dual accumulator)
    scores_mma<<<dim3(16, 8, 8), 512, SC_SMEM>>>(pQf, pQ2f, pKmf, pKvf, pS);
    // 6. softmax -> attn fp16
    softmax_rows<<<8192, 256>>>(pS, pAt);
    // 7. attn @ V_sample (mode 2, batched) -> Oa fp16
    mma_nt_1p<<<dim3(6, 8, 8), 512, P1_SMEM>>>(pAt, pVt, 2048, 2,
        (size_t)1024 * 2048, (size_t)768 * 2048, (size_t)1024 * 768,
        nullptr, nullptr, pOa, nullptr, nullptr, nullptr);
    // 8. gated output projection (mode 3)
    mma_nt_1p<<<dim3(6, 64), 512, P1_SMEM>>>(pOa, pwof, 768, 3,
        0, 0, 0, bo, out, nullptr, nullptr, query, gate);
}

// round 16
// speedup vs baseline: 1.2008x; 1.2008x over previous
#include <cuda_runtime.h>
#include <cuda_bf16.h>
#include <cuda_fp16.h>
#include <math.h>
#include <stdint.h>

#define BETA_C 2.35f

// ---------------- scratch (device globals; allocation-free) ----------------
__device__ float g_S[8 * 1024 * 2048];   // scores (fp32, pre-softmax)

// fp16 operands
__device__ __align__(256) __half g_qf   [8192  * 768];      // query fp16
__device__ __align__(256) __half g_cxf  [16384 * 768];      // context fp16
__device__ __align__(256) __half g_wqf  [768  * 768];
__device__ __align__(256) __half g_wkf  [1536 * 768];
__device__ __align__(256) __half g_wvf  [1536 * 768];
__device__ __align__(256) __half g_wof  [768  * 768];
__device__ __align__(256) __half g_Qf   [8192 * 768];       // Q fp16
__device__ __align__(256) __half g_Q2f  [8192 * 768];       // Q^2 fp16
__device__ __align__(256) __half g_Kmu16[16384 * 768];      // K_mu raw fp16 (pre-LN)
__device__ __align__(256) __half g_Kvf  [16384 * 768];      // softplus K var fp16
__device__ __align__(256) __half g_Kmf  [16384 * 768];      // LN(K_mu) fp16
__device__ __align__(256) __half g_Vmu16[16384 * 768];      // V_mu raw fp16 (pre-LN)
__device__ __align__(256) __half g_Vv16 [16384 * 768];      // softplus V var fp16
__device__ __align__(256) __half g_Vs   [16384 * 768];      // V_sample fp16 (row-major)
__device__ __align__(256) __half g_At   [8 * 1024 * 2048];  // attn fp16
__device__ __align__(256) __half g_Vt   [8 * 768 * 2048];   // V_sample^T fp16
__device__ __align__(256) __half g_Oa   [8192 * 768];       // attn@V fp16

__device__ __forceinline__ float softplus_eps(float x) {
    return (x > 20.f ? x : log1pf(expf(x))) + 1e-6f;
}
__device__ __forceinline__ uint32_t smem_u32(const void* p) {
    uint32_t a;
    asm("{ .reg .u64 t; cvta.to.shared.u64 t, %1; cvt.u32.u64 %0, t; }" : "=r"(a) : "l"(p));
    return a;
}
#define CP_COMMIT() asm volatile("cp.async.commit_group;" ::: "memory")
#define CP_WAIT2()  asm volatile("cp.async.wait_group 2;" ::: "memory")
#define CP_WAIT1()  asm volatile("cp.async.wait_group 1;" ::: "memory")
#define CP_WAIT0()  asm volatile("cp.async.wait_group 0;" ::: "memory")

__device__ __forceinline__ uint32_t swz128(uint32_t o) { return o ^ ((o >> 3) & 0x70u); }

__device__ __forceinline__ void ldsm_x4(uint32_t addr, uint32_t& r0, uint32_t& r1,
                                        uint32_t& r2, uint32_t& r3) {
    asm volatile("ldmatrix.sync.aligned.m8n8.x4.shared.b16 {%0,%1,%2,%3}, [%4];"
                 : "=r"(r0), "=r"(r1), "=r"(r2), "=r"(r3) : "r"(addr));
}
__device__ __forceinline__ void mma_f16(float* c, const uint32_t* a, const uint32_t* b) {
    asm volatile(
        "mma.sync.aligned.m16n8k16.row.col.f32.f16.f16.f32 "
        "{%0,%1,%2,%3}, {%4,%5,%6,%7}, {%8,%9}, {%0,%1,%2,%3};"
        : "+f"(c[0]), "+f"(c[1]), "+f"(c[2]), "+f"(c[3])
        : "r"(a[0]), "r"(a[1]), "r"(a[2]), "r"(a[3]), "r"(b[0]), "r"(b[1]));
}
__device__ __forceinline__ uint32_t pack_f16(float v0, float v1) {
    __half2 h = __floats2half2_rn(v0, v1);
    return *(uint32_t*)&h;
}

// =====================================================================
// fp32 -> fp16 converter
// =====================================================================
__global__ __launch_bounds__(256) void tohalf(const float* __restrict__ x,
                                              __half* __restrict__ y, int n4)
{
    int i = blockIdx.x * 256 + threadIdx.x;
    if (i >= n4) return;
    float4 v = ((const float4*)x)[i];
    ((uint2*)y)[i] = make_uint2(pack_f16(v.x, v.y), pack_f16(v.z, v.w));
}

// =====================================================================
// fp16 HMMA core: one 64-K chunk, A tile @abase, B tile @bbase (SW128)
// =====================================================================
__device__ __forceinline__ void mma_compute_1pass(
    float acc[2][4][4], uint32_t abase, uint32_t bbase, int wm, int wn, int lane)
{
    const int arow  = lane & 15;
    const int khalf = lane >> 4;
#pragma unroll
    for (int ks = 0; ks < 4; ks++) {
        const uint32_t kb = ks * 32 + khalf * 16;
        uint32_t Ah[2][4], Bh[4][2];
#pragma unroll
        for (int mi = 0; mi < 2; mi++) {
            uint32_t r = (uint32_t)((wm * 32 + mi * 16 + arow) * 128) + kb;
            ldsm_x4(abase + swz128(r), Ah[mi][0], Ah[mi][1], Ah[mi][2], Ah[mi][3]);
        }
#pragma unroll
        for (int nf = 0; nf < 2; nf++) {
            uint32_t r = (uint32_t)((wn * 32 + nf * 16 + arow) * 128) + kb;
            uint32_t r0, r1, r2, r3;
            ldsm_x4(bbase + swz128(r), r0, r1, r2, r3);
            Bh[nf * 2 + 0][0] = r0; Bh[nf * 2 + 0][1] = r2;
            Bh[nf * 2 + 1][0] = r1; Bh[nf * 2 + 1][1] = r3;
        }
#pragma unroll
        for (int mi = 0; mi < 2; mi++)
#pragma unroll
            for (int ni = 0; ni < 4; ni++)
                mma_f16(acc[mi][ni], Ah[mi], Bh[ni]);
    }
}

// tile loader: 128 rows x 64 x 16-bit (128B) from k-major gmem, SW128 swizzle
__device__ __forceinline__ void load_tile(uint32_t sdst, const uint16_t* __restrict__ src,
                                          size_t row0, int ldK, int k0, int tid)
{
#pragma unroll
    for (int i = 0; i < 2; i++) {
        int seg = tid + (i << 9);
        int row = seg >> 3;
        int sc  = seg & 7;
        const void* g = (const void*)(src + (row0 + row) * (size_t)ldK + k0 + sc * 8);
        uint32_t off = swz128((uint32_t)(row * 128 + sc * 16));
        asm volatile("cp.async.cg.shared.global [%0], [%1], 16;" :: "r"(sdst + off), "l"(g));
    }
}

#define P1_SMEM 131072
#define SC_SMEM 131072

// =====================================================================
// 1-pass fp16 NT GEMM: C[M,N] = A[M,K] x B[N,K]^T
// 4 smem buffers, lookahead 3, one __syncthreads per chunk.
// mode 0: KV proj (N=1536) -> oh = mu fp16 (col<768); oh2 = softplus var fp16
// mode 2: AV (batched)     -> oh = fp16 (no bias)
// mode 3: O proj           -> f0 = g*(acc+bias)+(1-g)*query fp32
// mode 4: Q proj           -> oh = Q fp16; oh2 = Q^2 fp16 (bias)
// =====================================================================
__global__ __launch_bounds__(512, 1) void mma_nt_1p(
    const __half* __restrict__ A, const __half* __restrict__ B,
    int K, int mode,
    size_t sAb, size_t sBb, size_t sCb,
    const float* __restrict__ bias,
    float* __restrict__ f0,
    __half* __restrict__ oh, __half* __restrict__ oh2,
    const float* __restrict__ query, const float* __restrict__ gate)
{
    extern __shared__ char smem[];
    const uint32_t sb = smem_u32(smem);
    const int tid  = threadIdx.x;
    const int wid  = tid >> 5;
    const int lane = tid & 31;
    const int wm = wid >> 2;
    const int wn = wid & 3;
    const int z  = blockIdx.z;

    const uint16_t* pA = (const uint16_t*)A + (size_t)z * sAb;
    const uint16_t* pB = (const uint16_t*)B + (size_t)z * sBb;
    const size_t arow0 = (size_t)blockIdx.y * 128;
    const size_t brow0 = (size_t)blockIdx.x * 128;

    float acc[2][4][4];
#pragma unroll
    for (int mi = 0; mi < 2; mi++)
#pragma unroll
        for (int ni = 0; ni < 4; ni++)
#pragma unroll
            for (int r = 0; r < 4; r++) acc[mi][ni][r] = 0.f;

    const int nc = K >> 6;   // always >= 12
#pragma unroll
    for (int p = 0; p < 3; p++) {
        uint32_t buf = sb + (uint32_t)p * 32768u;
        load_tile(buf,         pA, arow0, K, p * 64, tid);
        load_tile(buf + 16384, pB, brow0, K, p * 64, tid);
        CP_COMMIT();
    }

    for (int c = 0; c < nc; c++) {
        if (c < nc - 2)      { CP_WAIT2(); }
        else if (c < nc - 1) { CP_WAIT1(); }
        else                 { CP_WAIT0(); }
        __syncthreads();
        uint32_t buf = sb + (uint32_t)(c & 3) * 32768u;
        mma_compute_1pass(acc, buf, buf + 16384, wm, wn, lane);
        if (c + 3 < nc) {
            uint32_t lb = sb + (uint32_t)((c + 3) & 3) * 32768u;
            load_tile(lb,         pA, arow0, K, (c + 3) * 64, tid);
            load_tile(lb + 16384, pB, brow0, K, (c + 3) * 64, tid);
            CP_COMMIT();
        }
    }

    float gg = 0.f, og = 0.f;
    if (mode == 3) { gg = 1.f / (1.f + expf(-gate[0])); og = 1.f - gg; }

#pragma unroll
    for (int mi = 0; mi < 2; mi++) {
#pragma unroll
        for (int ni = 0; ni < 4; ni++) {
            size_t row = (size_t)blockIdx.y * 128 + wm * 32 + mi * 16 + (lane >> 2);
            int col = blockIdx.x * 128 + wn * 32 + ni * 8 + (lane & 3) * 2;
#pragma unroll
            for (int h = 0; h < 2; h++) {
                size_t r = row + h * 8;
                float v0 = acc[mi][ni][2 * h + 0];
                float v1 = acc[mi][ni][2 * h + 1];
                if (mode == 0) {
                    v0 += bias[col]; v1 += bias[col + 1];
                    if (col < 768) {
                        *(uint32_t*)(oh + r * 768 + col) = pack_f16(v0, v1);
                    } else {
                        *(uint32_t*)(oh2 + r * 768 + (col - 768)) =
                            pack_f16(softplus_eps(v0), softplus_eps(v1));
                    }
                } else if (mode == 2) {
                    *(uint32_t*)(oh + (size_t)z * sCb + r * 768 + col) = pack_f16(v0, v1);
                } else if (mode == 3) {
                    size_t idx = r * 768 + col;
                    float2 qv = *(const float2*)(query + idx);
                    float2 o;
                    o.x = gg * (v0 + bias[col])     + og * qv.x;
                    o.y = gg * (v1 + bias[col + 1]) + og * qv.y;
                    *(float2*)(f0 + idx) = o;
                } else {  // mode 4: Q proj
                    v0 += bias[col]; v1 += bias[col + 1];
                    size_t idx = r * 768 + col;
                    *(uint32_t*)(oh  + idx) = pack_f16(v0, v1);
                    *(uint32_t*)(oh2 + idx) = pack_f16(v0 * v0, v1 * v1);
                }
            }
        }
    }
}

// =====================================================================
// LN + V-sample (R14 structure, fp16 in/out, coalesced)
// one row/block; Kmf <- fp16(LN(Kmu16)); Vs <- fp16(LN(Vmu16)+sqrt(Vv16)*eps)
// =====================================================================
__global__ __launch_bounds__(256) void ln_fuse(
    const float* __restrict__ kg, const float* __restrict__ kb,
    const float* __restrict__ vg, const float* __restrict__ vb,
    const float* __restrict__ eps)
{
    const size_t row = blockIdx.x;
    const int tid = threadIdx.x;
    const size_t base = row * 768;
    __shared__ float s1[8], s2[8];

    // ---- K LN ----
    float x0 = __half2float(g_Kmu16[base + tid]);
    float x1 = __half2float(g_Kmu16[base + tid + 256]);
    float x2 = __half2float(g_Kmu16[base + tid + 512]);
    float s = x0 + x1 + x2;
    float q = fmaf(x0, x0, fmaf(x1, x1, x2 * x2));
#pragma unroll
    for (int o = 16; o > 0; o >>= 1) {
        s += __shfl_down_sync(0xffffffffu, s, o);
        q += __shfl_down_sync(0xffffffffu, q, o);
    }
    if ((tid & 31) == 0) { s1[tid >> 5] = s; s2[tid >> 5] = q; }
    __syncthreads();
    float ts = 0.f, tq = 0.f;
#pragma unroll
    for (int i = 0; i < 8; i++) { ts += s1[i]; tq += s2[i]; }
    float m    = ts * (1.f / 768.f);
    float var  = tq * (1.f / 768.f) - m * m;
    float rstd = rsqrtf(var + 1e-5f);
    g_Kmf[base + tid]       = __float2half_rn((x0 - m) * rstd * kg[tid]       + kb[tid]);
    g_Kmf[base + tid + 256] = __float2half_rn((x1 - m) * rstd * kg[tid + 256] + kb[tid + 256]);
    g_Kmf[base + tid + 512] = __float2half_rn((x2 - m) * rstd * kg[tid + 512] + kb[tid + 512]);
    __syncthreads();

    // ---- V LN + sample ----
    x0 = __half2float(g_Vmu16[base + tid]);
    x1 = __half2float(g_Vmu16[base + tid + 256]);
    x2 = __half2float(g_Vmu16[base + tid + 512]);
    s = x0 + x1 + x2;
    q = fmaf(x0, x0, fmaf(x1, x1, x2 * x2));
#pragma unroll
    for (int o = 16; o > 0; o >>= 1) {
        s += __shfl_down_sync(0xffffffffu, s, o);
        q += __shfl_down_sync(0xffffffffu, q, o);
    }
    if ((tid & 31) == 0) { s1[tid >> 5] = s; s2[tid >> 5] = q; }
    __syncthreads();
    ts = 0.f; tq = 0.f;
#pragma unroll
    for (int i = 0; i < 8; i++) { ts += s1[i]; tq += s2[i]; }
    m    = ts * (1.f / 768.f);
    var  = tq * (1.f / 768.f) - m * m;
    rstd = rsqrtf(var + 1e-5f);
#pragma unroll
    for (int p = 0; p < 3; p++) {
        int c = tid + p * 256;
        float x = (p == 0 ? x0 : (p == 1 ? x1 : x2));
        float v = (x - m) * rstd * vg[c] + vb[c]
                + sqrtf(__half2float(g_Vv16[base + c])) * eps[base + c];
        g_Vs[base + c] = __float2half_rn(v);
    }
}

// =====================================================================
// Transpose V_sample fp16 [b,2048,768] -> Vt fp16 [b,768,2048]
// (padded float smem tile; fully coalesced gmem on both sides)
// =====================================================================
__global__ void transpose_v(const __half* __restrict__ V, __half* __restrict__ T)
{
    __shared__ __half t[32][40];
    const int b  = blockIdx.z;
    const int k0 = blockIdx.x * 32;
    const int c0 = blockIdx.y * 32;
    const int tx = threadIdx.x, ty = threadIdx.y;
    const __half* Vb = V + (size_t)b * 2048 * 768;
#pragma unroll
    for (int j = 0; j < 4; j++) {
        int kr = ty + j * 8;
        t[kr][tx] = Vb[(size_t)(k0 + kr) * 768 + c0 + tx];
    }
    __syncthreads();
    const size_t obase = (size_t)b * 768 * 2048;
#pragma unroll
    for (int j = 0; j < 4; j++) {
        int cr = ty + j * 8;
        T[obase + (size_t)(c0 + cr) * 2048 + k0 + tx] = t[tx][cr];
    }
}

// =====================================================================
// Scores, all 1-pass fp16 (dual accumulator) — R14 proven config:
// 2 x 64KB buffers, wait_group 1.
// S[b,q,k] = (Q.Kmu)/sqrt(C) - BETA*sqrt((Q^2 . Kvar)/C)
// =====================================================================
__global__ __launch_bounds__(512, 1) void scores_mma(
    const __half* __restrict__ qf,  const __half* __restrict__ q2f,
    const __half* __restrict__ kmf, const __half* __restrict__ kvf,
    float* __restrict__ S)
{
    extern __shared__ char smem[];
    const uint32_t sb = smem_u32(smem);
    const int tid  = threadIdx.x;
    const int wid  = tid >> 5;
    const int lane = tid & 31;
    const int wm = wid >> 2;
    const int wn = wid & 3;
    const int b  = blockIdx.z;
    const int mt = blockIdx.y;
    const int nt = blockIdx.x;
    const size_t qrow0 = (size_t)b * 1024 + (size_t)mt * 128;
    const size_t krow0 = (size_t)b * 2048 + (size_t)nt * 128;

    float accM[2][4][4], accV[2][4][4];
#pragma unroll
    for (int mi = 0; mi < 2; mi++)
#pragma unroll
        for (int ni = 0; ni < 4; ni++)
#pragma unroll
            for (int r = 0; r < 4; r++) { accM[mi][ni][r] = 0.f; accV[mi][ni][r] = 0.f; }

    const uint16_t* pq  = (const uint16_t*)qf;
    const uint16_t* pq2 = (const uint16_t*)q2f;
    const uint16_t* pkm = (const uint16_t*)kmf;
    const uint16_t* pkv = (const uint16_t*)kvf;

#pragma unroll
    for (int p = 0; p < 2; p++) {
        uint32_t buf = sb + (uint32_t)p * 65536u;
        load_tile(buf,         pq,  qrow0, 768, p * 64, tid);
        load_tile(buf + 16384, pkm, krow0, 768, p * 64, tid);
        load_tile(buf + 32768, pq2, qrow0, 768, p * 64, tid);
        load_tile(buf + 49152, pkv, krow0, 768, p * 64, tid);
        CP_COMMIT();
    }

    for (int c = 0; c < 12; c++) {
        if (c < 11) { CP_WAIT1(); } else { CP_WAIT0(); }
        __syncthreads();
        uint32_t buf = sb + (uint32_t)(c & 1) * 65536u;
        mma_compute_1pass(accM, buf,         buf + 16384, wm, wn, lane);
        mma_compute_1pass(accV, buf + 32768, buf + 49152, wm, wn, lane);
        __syncthreads();
        if (c + 2 < 12) {
            load_tile(buf,         pq,  qrow0, 768, (c + 2) * 64, tid);
            load_tile(buf + 16384, pkm, krow0, 768, (c + 2) * 64, tid);
            load_tile(buf + 32768, pq2, qrow0, 768, (c + 2) * 64, tid);
            load_tile(buf + 49152, pkv, krow0, 768, (c + 2) * 64, tid);
            CP_COMMIT();
        }
    }

    const float inv_scale = 0.03608439182435161f;  // 1/sqrt(768)
    const float invC = 1.0f / 768.0f;
    float* Sbase = S + (qrow0 * 2048) + (size_t)nt * 128;
#pragma unroll
    for (int mi = 0; mi < 2; mi++) {
#pragma unroll
        for (int ni = 0; ni < 4; ni++) {
            int col = wn * 32 + ni * 8 + (lane & 3) * 2;
            int row0 = wm * 32 + mi * 16 + (lane >> 2);
            float2 v0, v1;
            v0.x = accM[mi][ni][0] * inv_scale - BETA_C * sqrtf(accV[mi][ni][0] * invC);
            v0.y = accM[mi][ni][1] * inv_scale - BETA_C * sqrtf(accV[mi][ni][1] * invC);
            v1.x = accM[mi][ni][2] * inv_scale - BETA_C * sqrtf(accV[mi][ni][2] * invC);
            v1.y = accM[mi][ni][3] * inv_scale - BETA_C * sqrtf(accV[mi][ni][3] * invC);
            *(float2*)(Sbase + (size_t)row0 * 2048 + col)       = v0;
            *(float2*)(Sbase + (size_t)(row0 + 8) * 2048 + col) = v1;
        }
    }
}

// =====================================================================
// Row softmax over 2048 -> attn fp16
// =====================================================================
__global__ __launch_bounds__(256) void softmax_rows(
    const float* __restrict__ S, __half* __restrict__ At)
{
    const size_t row = blockIdx.x;
    const float* r = S + row * 2048;
    const int tid = threadIdx.x;
    __shared__ float sh[8];

    float4 v0 = *(const float4*)(r + tid * 4);
    float4 v1 = *(const float4*)(r + 1024 + tid * 4);

    float mx = fmaxf(fmaxf(fmaxf(v0.x, v0.y), fmaxf(v0.z, v0.w)),
                     fmaxf(fmaxf(v1.x, v1.y), fmaxf(v1.z, v1.w)));
#pragma unroll
    for (int o = 16; o > 0; o >>= 1) mx = fmaxf(mx, __shfl_xor_sync(0xffffffffu, mx, o));
    if ((tid & 31) == 0) sh[tid >> 5] = mx;
    __syncthreads();
    mx = sh[0];
#pragma unroll
    for (int i = 1; i < 8; i++) mx = fmaxf(mx, sh[i]);
    __syncthreads();

    v0.x = expf(v0.x - mx); v0.y = expf(v0.y - mx); v0.z = expf(v0.z - mx); v0.w = expf(v0.w - mx);
    v1.x = expf(v1.x - mx); v1.y = expf(v1.y - mx); v1.z = expf(v1.z - mx); v1.w = expf(v1.w - mx);
    float sum = (v0.x + v0.y + v0.z + v0.w) + (v1.x + v1.y + v1.z + v1.w);
#pragma unroll
    for (int o = 16; o > 0; o >>= 1) sum += __shfl_xor_sync(0xffffffffu, sum, o);
    if ((tid & 31) == 0) sh[tid >> 5] = sum;
    __syncthreads();
    float tot = 0.f;
#pragma unroll
    for (int i = 0; i < 8; i++) tot += sh[i];
    float inv = 1.f / tot;

    size_t i0 = row * 2048 + tid * 4;
    size_t i1 = i0 + 1024;
    *(uint32_t*)(At + i0)     = pack_f16(v0.x * inv, v0.y * inv);
    *(uint32_t*)(At + i0 + 2) = pack_f16(v0.z * inv, v0.w * inv);
    *(uint32_t*)(At + i1)     = pack_f16(v1.x * inv, v1.y * inv);
    *(uint32_t*)(At + i1 + 2) = pack_f16(v1.z * inv, v1.w * inv);
}

// =====================================================================
extern "C" void kernel_launch(void* const* d_in, const int* in_sizes, int n_in,
                              void* d_out, int out_size)
{
    const float* query     = (const float*)d_in[0];
    const float* context   = (const float*)d_in[1];
    const float* eps_noise = (const float*)d_in[2];
    const float* Wq        = (const float*)d_in[3];
    const float* bq        = (const float*)d_in[4];
    const float* Wk        = (const float*)d_in[5];
    const float* bk        = (const float*)d_in[6];
    const float* Wv        = (const float*)d_in[7];
    const float* bv        = (const float*)d_in[8];
    const float* Wo        = (const float*)d_in[9];
    const float* bo        = (const float*)d_in[10];
    const float* ln_k_g    = (const float*)d_in[11];
    const float* ln_k_b    = (const float*)d_in[12];
    const float* ln_v_g    = (const float*)d_in[13];
    const float* ln_v_b    = (const float*)d_in[14];
    const float* gate      = (const float*)d_in[15];
    float* out = (float*)d_out;

    float* pS;
    cudaGetSymbolAddress((void**)&pS, g_S);

    __half *pqf, *pcxf, *pwqf, *pwkf, *pwvf, *pwof;
    __half *pQf, *pQ2f, *pKmu16, *pKvf, *pKmf, *pVmu16, *pVv16, *pVs, *pAt, *pVt, *pOa;
    cudaGetSymbolAddress((void**)&pqf,    g_qf);
    cudaGetSymbolAddress((void**)&pcxf,   g_cxf);
    cudaGetSymbolAddress((void**)&pwqf,   g_wqf);
    cudaGetSymbolAddress((void**)&pwkf,   g_wkf);
    cudaGetSymbolAddress((void**)&pwvf,   g_wvf);
    cudaGetSymbolAddress((void**)&pwof,   g_wof);
    cudaGetSymbolAddress((void**)&pQf,    g_Qf);
    cudaGetSymbolAddress((void**)&pQ2f,   g_Q2f);
    cudaGetSymbolAddress((void**)&pKmu16, g_Kmu16);
    cudaGetSymbolAddress((void**)&pKvf,   g_Kvf);
    cudaGetSymbolAddress((void**)&pKmf,   g_Kmf);
    cudaGetSymbolAddress((void**)&pVmu16, g_Vmu16);
    cudaGetSymbolAddress((void**)&pVv16,  g_Vv16);
    cudaGetSymbolAddress((void**)&pVs,    g_Vs);
    cudaGetSymbolAddress((void**)&pAt,    g_At);
    cudaGetSymbolAddress((void**)&pVt,    g_Vt);
    cudaGetSymbolAddress((void**)&pOa,    g_Oa);

    static int cfg_done = 0;
    if (!cfg_done) {
        cudaFuncSetAttribute(scores_mma, cudaFuncAttributeMaxDynamicSharedMemorySize, SC_SMEM);
        cudaFuncSetAttribute(mma_nt_1p,  cudaFuncAttributeMaxDynamicSharedMemorySize, P1_SMEM);
        cfg_done = 1;
    }

    // 0. operand conversions (all fp16)
    tohalf<<<6144,  256>>>(query,   pqf,  6291456 / 4);
    tohalf<<<12288, 256>>>(context, pcxf, 12582912 / 4);
    tohalf<<<576,   256>>>(Wq, pwqf, 589824 / 4);
    tohalf<<<1152,  256>>>(Wk, pwkf, 1179648 / 4);
    tohalf<<<1152,  256>>>(Wv, pwvf, 1179648 / 4);
    tohalf<<<576,   256>>>(Wo, pwof, 589824 / 4);

    // 1. Q projection (mode 4) -> Qf, Q2f fp16
    mma_nt_1p<<<dim3(6, 64), 512, P1_SMEM>>>(pqf, pwqf, 768, 4,
        0, 0, 0, bq, nullptr, pQf, pQ2f, nullptr, nullptr);
    // 2. K projection (mode 0, N=1536) -> Kmu16 fp16 / Kvf fp16
    mma_nt_1p<<<dim3(12, 128), 512, P1_SMEM>>>(pcxf, pwkf, 768, 0,
        0, 0, 0, bk, nullptr, pKmu16, pKvf, nullptr, nullptr);
    // 3. V projection (mode 0, N=1536) -> Vmu16 fp16 / Vv16 fp16
    mma_nt_1p<<<dim3(12, 128), 512, P1_SMEM>>>(pcxf, pwvf, 768, 0,
        0, 0, 0, bv, nullptr, pVmu16, pVv16, nullptr, nullptr);
    // 4. LN + V sampling -> Kmf fp16, Vs fp16
    ln_fuse<<<16384, 256>>>(ln_k_g, ln_k_b, ln_v_g, ln_v_b, eps_noise);
    // 5. transpose V_sample -> Vt fp16 (coalesced)
    transpose_v<<<dim3(64, 24, 8), dim3(32, 8)>>>(pVs, pVt);
    // 6. scores (all 1-pass fp16, dual accumulator)
    scores_mma<<<dim3(16, 8, 8), 512, SC_SMEM>>>(pQf, pQ2f, pKmf, pKvf, pS);
    // 7. softmax -> attn fp16
    softmax_rows<<<8192, 256>>>(pS, pAt);
    // 8. attn @ V_sample (mode 2, batched) -> Oa fp16
    mma_nt_1p<<<dim3(6, 8, 8), 512, P1_SMEM>>>(pAt, pVt, 2048, 2,
        (size_t)1024 * 2048, (size_t)768 * 2048, (size_t)1024 * 768,
        nullptr, nullptr, pOa, nullptr, nullptr, nullptr);
    // 9. gated output projection (mode 3)
    mma_nt_1p<<<dim3(6, 64), 512, P1_SMEM>>>(pOa, pwof, 768, 3,
        0, 0, 0, bo, out, nullptr, nullptr, query, gate);
}

// round 17
// speedup vs baseline: 1.2250x; 1.0201x over previous
#include <cuda_runtime.h>
#include <cuda_bf16.h>
#include <cuda_fp16.h>
#include <math.h>
#include <stdint.h>

#define BETA_C 2.35f

// ---------------- scratch (device globals; allocation-free) ----------------
__device__ float g_S[8 * 1024 * 2048];   // scores (fp32, pre-softmax)

// fp16 operands
__device__ __align__(256) __half g_qf   [8192  * 768];      // query fp16
__device__ __align__(256) __half g_cxf  [16384 * 768];      // context fp16
__device__ __align__(256) __half g_wqf  [768  * 768];
__device__ __align__(256) __half g_wkf  [1536 * 768];
__device__ __align__(256) __half g_wvf  [1536 * 768];
__device__ __align__(256) __half g_wof  [768  * 768];
__device__ __align__(256) __half g_Qf   [8192 * 768];       // Q fp16
__device__ __align__(256) __half g_Q2f  [8192 * 768];       // Q^2 fp16
__device__ __align__(256) __half g_Kmu16[16384 * 768];      // K_mu raw fp16 (pre-LN)
__device__ __align__(256) __half g_Kvf  [16384 * 768];      // softplus K var fp16
__device__ __align__(256) __half g_Kmf  [16384 * 768];      // LN(K_mu) fp16
__device__ __align__(256) __half g_Vmu16[16384 * 768];      // V_mu raw fp16 (pre-LN)
__device__ __align__(256) __half g_Vv16 [16384 * 768];      // softplus V var fp16
__device__ __align__(256) __half g_Vs   [16384 * 768];      // V_sample fp16 (row-major)
__device__ __align__(256) __half g_At   [8 * 1024 * 2048];  // attn fp16
__device__ __align__(256) __half g_Vt   [8 * 768 * 2048];   // V_sample^T fp16
__device__ __align__(256) __half g_Oa   [8192 * 768];       // attn@V fp16

__device__ __forceinline__ float softplus_eps(float x) {
    return (x > 20.f ? x : log1pf(expf(x))) + 1e-6f;
}
__device__ __forceinline__ uint32_t smem_u32(const void* p) {
    uint32_t a;
    asm("{ .reg .u64 t; cvta.to.shared.u64 t, %1; cvt.u32.u64 %0, t; }" : "=r"(a) : "l"(p));
    return a;
}
#define CP_COMMIT() asm volatile("cp.async.commit_group;" ::: "memory")
#define CP_WAIT2()  asm volatile("cp.async.wait_group 2;" ::: "memory")
#define CP_WAIT1()  asm volatile("cp.async.wait_group 1;" ::: "memory")
#define CP_WAIT0()  asm volatile("cp.async.wait_group 0;" ::: "memory")

__device__ __forceinline__ uint32_t swz128(uint32_t o) { return o ^ ((o >> 3) & 0x70u); }

__device__ __forceinline__ void ldsm_x4(uint32_t addr, uint32_t& r0, uint32_t& r1,
                                        uint32_t& r2, uint32_t& r3) {
    asm volatile("ldmatrix.sync.aligned.m8n8.x4.shared.b16 {%0,%1,%2,%3}, [%4];"
                 : "=r"(r0), "=r"(r1), "=r"(r2), "=r"(r3) : "r"(addr));
}
__device__ __forceinline__ void mma_f16(float* c, const uint32_t* a, const uint32_t* b) {
    asm volatile(
        "mma.sync.aligned.m16n8k16.row.col.f32.f16.f16.f32 "
        "{%0,%1,%2,%3}, {%4,%5,%6,%7}, {%8,%9}, {%0,%1,%2,%3};"
        : "+f"(c[0]), "+f"(c[1]), "+f"(c[2]), "+f"(c[3])
        : "r"(a[0]), "r"(a[1]), "r"(a[2]), "r"(a[3]), "r"(b[0]), "r"(b[1]));
}
__device__ __forceinline__ uint32_t pack_f16(float v0, float v1) {
    __half2 h = __floats2half2_rn(v0, v1);
    return *(uint32_t*)&h;
}

// =====================================================================
// merged fp32 -> fp16 converter: all 6 inputs in one launch
// segments (in float4 units): query 1572864 | context 3145728 | Wq 147456 |
// Wk 294912 | Wv 294912 | Wo 147456 ; total 5603328
// =====================================================================
__global__ __launch_bounds__(256) void tohalf_all(
    const float* __restrict__ q,  const float* __restrict__ cx,
    const float* __restrict__ wq, const float* __restrict__ wk,
    const float* __restrict__ wv, const float* __restrict__ wo)
{
    const int i = blockIdx.x * 256 + threadIdx.x;  // grid exactly covers total
    const float* src;
    __half* dst;
    int off;
    if (i < 1572864)      { src = q;  dst = g_qf;  off = i; }
    else if (i < 4718592) { src = cx; dst = g_cxf; off = i - 1572864; }
    else if (i < 4866048) { src = wq; dst = g_wqf; off = i - 4718592; }
    else if (i < 5160960) { src = wk; dst = g_wkf; off = i - 4866048; }
    else if (i < 5455872) { src = wv; dst = g_wvf; off = i - 5160960; }
    else                  { src = wo; dst = g_wof; off = i - 5455872; }
    float4 v = ((const float4*)src)[off];
    ((uint2*)dst)[off] = make_uint2(pack_f16(v.x, v.y), pack_f16(v.z, v.w));
}

// =====================================================================
// fp16 HMMA core: one 64-K chunk, A tile @abase, B tile @bbase (SW128)
// =====================================================================
__device__ __forceinline__ void mma_compute_1pass(
    float acc[2][4][4], uint32_t abase, uint32_t bbase, int wm, int wn, int lane)
{
    const int arow  = lane & 15;
    const int khalf = lane >> 4;
#pragma unroll
    for (int ks = 0; ks < 4; ks++) {
        const uint32_t kb = ks * 32 + khalf * 16;
        uint32_t Ah[2][4], Bh[4][2];
#pragma unroll
        for (int mi = 0; mi < 2; mi++) {
            uint32_t r = (uint32_t)((wm * 32 + mi * 16 + arow) * 128) + kb;
            ldsm_x4(abase + swz128(r), Ah[mi][0], Ah[mi][1], Ah[mi][2], Ah[mi][3]);
        }
#pragma unroll
        for (int nf = 0; nf < 2; nf++) {
            uint32_t r = (uint32_t)((wn * 32 + nf * 16 + arow) * 128) + kb;
            uint32_t r0, r1, r2, r3;
            ldsm_x4(bbase + swz128(r), r0, r1, r2, r3);
            Bh[nf * 2 + 0][0] = r0; Bh[nf * 2 + 0][1] = r2;
            Bh[nf * 2 + 1][0] = r1; Bh[nf * 2 + 1][1] = r3;
        }
#pragma unroll
        for (int mi = 0; mi < 2; mi++)
#pragma unroll
            for (int ni = 0; ni < 4; ni++)
                mma_f16(acc[mi][ni], Ah[mi], Bh[ni]);
    }
}

// tile loader: 128 rows x 64 x 16-bit (128B) from k-major gmem, SW128 swizzle
__device__ __forceinline__ void load_tile(uint32_t sdst, const uint16_t* __restrict__ src,
                                          size_t row0, int ldK, int k0, int tid)
{
#pragma unroll
    for (int i = 0; i < 2; i++) {
        int seg = tid + (i << 9);
        int row = seg >> 3;
        int sc  = seg & 7;
        const void* g = (const void*)(src + (row0 + row) * (size_t)ldK + k0 + sc * 8);
        uint32_t off = swz128((uint32_t)(row * 128 + sc * 16));
        asm volatile("cp.async.cg.shared.global [%0], [%1], 16;" :: "r"(sdst + off), "l"(g));
    }
}

#define P1_SMEM 131072
#define SC_SMEM 196608

// =====================================================================
// 1-pass fp16 NT GEMM: C[M,N] = A[M,K] x B[N,K]^T
// 4 smem buffers, lookahead 3, one __syncthreads per chunk.
// mode 0: KV proj (N=1536) -> oh = mu fp16 (col<768); oh2 = softplus var fp16
// mode 2: AV (batched)     -> oh = fp16 (no bias)
// mode 3: O proj           -> f0 = g*(acc+bias)+(1-g)*query fp32
// mode 4: Q proj           -> oh = Q fp16; oh2 = Q^2 fp16 (bias)
// =====================================================================
__global__ __launch_bounds__(512, 1) void mma_nt_1p(
    const __half* __restrict__ A, const __half* __restrict__ B,
    int K, int mode,
    size_t sAb, size_t sBb, size_t sCb,
    const float* __restrict__ bias,
    float* __restrict__ f0,
    __half* __restrict__ oh, __half* __restrict__ oh2,
    const float* __restrict__ query, const float* __restrict__ gate)
{
    extern __shared__ char smem[];
    const uint32_t sb = smem_u32(smem);
    const int tid  = threadIdx.x;
    const int wid  = tid >> 5;
    const int lane = tid & 31;
    const int wm = wid >> 2;
    const int wn = wid & 3;
    const int z  = blockIdx.z;

    const uint16_t* pA = (const uint16_t*)A + (size_t)z * sAb;
    const uint16_t* pB = (const uint16_t*)B + (size_t)z * sBb;
    const size_t arow0 = (size_t)blockIdx.y * 128;
    const size_t brow0 = (size_t)blockIdx.x * 128;

    float acc[2][4][4];
#pragma unroll
    for (int mi = 0; mi < 2; mi++)
#pragma unroll
        for (int ni = 0; ni < 4; ni++)
#pragma unroll
            for (int r = 0; r < 4; r++) acc[mi][ni][r] = 0.f;

    const int nc = K >> 6;   // always >= 12
#pragma unroll
    for (int p = 0; p < 3; p++) {
        uint32_t buf = sb + (uint32_t)p * 32768u;
        load_tile(buf,         pA, arow0, K, p * 64, tid);
        load_tile(buf + 16384, pB, brow0, K, p * 64, tid);
        CP_COMMIT();
    }

    for (int c = 0; c < nc; c++) {
        if (c < nc - 2)      { CP_WAIT2(); }
        else if (c < nc - 1) { CP_WAIT1(); }
        else                 { CP_WAIT0(); }
        __syncthreads();
        uint32_t buf = sb + (uint32_t)(c & 3) * 32768u;
        mma_compute_1pass(acc, buf, buf + 16384, wm, wn, lane);
        if (c + 3 < nc) {
            uint32_t lb = sb + (uint32_t)((c + 3) & 3) * 32768u;
            load_tile(lb,         pA, arow0, K, (c + 3) * 64, tid);
            load_tile(lb + 16384, pB, brow0, K, (c + 3) * 64, tid);
            CP_COMMIT();
        }
    }

    float gg = 0.f, og = 0.f;
    if (mode == 3) { gg = 1.f / (1.f + expf(-gate[0])); og = 1.f - gg; }

#pragma unroll
    for (int mi = 0; mi < 2; mi++) {
#pragma unroll
        for (int ni = 0; ni < 4; ni++) {
            size_t row = (size_t)blockIdx.y * 128 + wm * 32 + mi * 16 + (lane >> 2);
            int col = blockIdx.x * 128 + wn * 32 + ni * 8 + (lane & 3) * 2;
#pragma unroll
            for (int h = 0; h < 2; h++) {
                size_t r = row + h * 8;
                float v0 = acc[mi][ni][2 * h + 0];
                float v1 = acc[mi][ni][2 * h + 1];
                if (mode == 0) {
                    v0 += bias[col]; v1 += bias[col + 1];
                    if (col < 768) {
                        *(uint32_t*)(oh + r * 768 + col) = pack_f16(v0, v1);
                    } else {
                        *(uint32_t*)(oh2 + r * 768 + (col - 768)) =
                            pack_f16(softplus_eps(v0), softplus_eps(v1));
                    }
                } else if (mode == 2) {
                    *(uint32_t*)(oh + (size_t)z * sCb + r * 768 + col) = pack_f16(v0, v1);
                } else if (mode == 3) {
                    size_t idx = r * 768 + col;
                    float2 qv = *(const float2*)(query + idx);
                    float2 o;
                    o.x = gg * (v0 + bias[col])     + og * qv.x;
                    o.y = gg * (v1 + bias[col + 1]) + og * qv.y;
                    *(float2*)(f0 + idx) = o;
                } else {  // mode 4: Q proj
                    v0 += bias[col]; v1 += bias[col + 1];
                    size_t idx = r * 768 + col;
                    *(uint32_t*)(oh  + idx) = pack_f16(v0, v1);
                    *(uint32_t*)(oh2 + idx) = pack_f16(v0 * v0, v1 * v1);
                }
            }
        }
    }
}

// =====================================================================
// LN + V-sample (fp16 in/out, coalesced)
// =====================================================================
__global__ __launch_bounds__(256) void ln_fuse(
    const float* __restrict__ kg, const float* __restrict__ kb,
    const float* __restrict__ vg, const float* __restrict__ vb,
    const float* __restrict__ eps)
{
    const size_t row = blockIdx.x;
    const int tid = threadIdx.x;
    const size_t base = row * 768;
    __shared__ float s1[8], s2[8];

    // ---- K LN ----
    float x0 = __half2float(g_Kmu16[base + tid]);
    float x1 = __half2float(g_Kmu16[base + tid + 256]);
    float x2 = __half2float(g_Kmu16[base + tid + 512]);
    float s = x0 + x1 + x2;
    float q = fmaf(x0, x0, fmaf(x1, x1, x2 * x2));
#pragma unroll
    for (int o = 16; o > 0; o >>= 1) {
        s += __shfl_down_sync(0xffffffffu, s, o);
        q += __shfl_down_sync(0xffffffffu, q, o);
    }
    if ((tid & 31) == 0) { s1[tid >> 5] = s; s2[tid >> 5] = q; }
    __syncthreads();
    float ts = 0.f, tq = 0.f;
#pragma unroll
    for (int i = 0; i < 8; i++) { ts += s1[i]; tq += s2[i]; }
    float m    = ts * (1.f / 768.f);
    float var  = tq * (1.f / 768.f) - m * m;
    float rstd = rsqrtf(var + 1e-5f);
    g_Kmf[base + tid]       = __float2half_rn((x0 - m) * rstd * kg[tid]       + kb[tid]);
    g_Kmf[base + tid + 256] = __float2half_rn((x1 - m) * rstd * kg[tid + 256] + kb[tid + 256]);
    g_Kmf[base + tid + 512] = __float2half_rn((x2 - m) * rstd * kg[tid + 512] + kb[tid + 512]);
    __syncthreads();

    // ---- V LN + sample ----
    x0 = __half2float(g_Vmu16[base + tid]);
    x1 = __half2float(g_Vmu16[base + tid + 256]);
    x2 = __half2float(g_Vmu16[base + tid + 512]);
    s = x0 + x1 + x2;
    q = fmaf(x0, x0, fmaf(x1, x1, x2 * x2));
#pragma unroll
    for (int o = 16; o > 0; o >>= 1) {
        s += __shfl_down_sync(0xffffffffu, s, o);
        q += __shfl_down_sync(0xffffffffu, q, o);
    }
    if ((tid & 31) == 0) { s1[tid >> 5] = s; s2[tid >> 5] = q; }
    __syncthreads();
    ts = 0.f; tq = 0.f;
#pragma unroll
    for (int i = 0; i < 8; i++) { ts += s1[i]; tq += s2[i]; }
    m    = ts * (1.f / 768.f);
    var  = tq * (1.f / 768.f) - m * m;
    rstd = rsqrtf(var + 1e-5f);
#pragma unroll
    for (int p = 0; p < 3; p++) {
        int c = tid + p * 256;
        float x = (p == 0 ? x0 : (p == 1 ? x1 : x2));
        float v = (x - m) * rstd * vg[c] + vb[c]
                + sqrtf(__half2float(g_Vv16[base + c])) * eps[base + c];
        g_Vs[base + c] = __float2half_rn(v);
    }
}

// =====================================================================
// Transpose V_sample fp16 [b,2048,768] -> Vt fp16 [b,768,2048]
// =====================================================================
__global__ void transpose_v(const __half* __restrict__ V, __half* __restrict__ T)
{
    __shared__ __half t[32][40];
    const int b  = blockIdx.z;
    const int k0 = blockIdx.x * 32;
    const int c0 = blockIdx.y * 32;
    const int tx = threadIdx.x, ty = threadIdx.y;
    const __half* Vb = V + (size_t)b * 2048 * 768;
#pragma unroll
    for (int j = 0; j < 4; j++) {
        int kr = ty + j * 8;
        t[kr][tx] = Vb[(size_t)(k0 + kr) * 768 + c0 + tx];
    }
    __syncthreads();
    const size_t obase = (size_t)b * 768 * 2048;
#pragma unroll
    for (int j = 0; j < 4; j++) {
        int cr = ty + j * 8;
        T[obase + (size_t)(c0 + cr) * 2048 + k0 + tx] = t[tx][cr];
    }
}

// =====================================================================
// Scores, all 1-pass fp16 (dual accumulator):
// 3 x 64KB buffers, lookahead 2, single __syncthreads per chunk.
// S[b,q,k] = (Q.Kmu)/sqrt(C) - BETA*sqrt((Q^2 . Kvar)/C)
// =====================================================================
__global__ __launch_bounds__(512, 1) void scores_mma(
    const __half* __restrict__ qf,  const __half* __restrict__ q2f,
    const __half* __restrict__ kmf, const __half* __restrict__ kvf,
    float* __restrict__ S)
{
    extern __shared__ char smem[];
    const uint32_t sb = smem_u32(smem);
    const int tid  = threadIdx.x;
    const int wid  = tid >> 5;
    const int lane = tid & 31;
    const int wm = wid >> 2;
    const int wn = wid & 3;
    const int b  = blockIdx.z;
    const int mt = blockIdx.y;
    const int nt = blockIdx.x;
    const size_t qrow0 = (size_t)b * 1024 + (size_t)mt * 128;
    const size_t krow0 = (size_t)b * 2048 + (size_t)nt * 128;

    float accM[2][4][4], accV[2][4][4];
#pragma unroll
    for (int mi = 0; mi < 2; mi++)
#pragma unroll
        for (int ni = 0; ni < 4; ni++)
#pragma unroll
            for (int r = 0; r < 4; r++) { accM[mi][ni][r] = 0.f; accV[mi][ni][r] = 0.f; }

    const uint16_t* pq  = (const uint16_t*)qf;
    const uint16_t* pq2 = (const uint16_t*)q2f;
    const uint16_t* pkm = (const uint16_t*)kmf;
    const uint16_t* pkv = (const uint16_t*)kvf;

    uint32_t bufsel[3] = {sb, sb + 65536u, sb + 131072u};
#pragma unroll
    for (int p = 0; p < 2; p++) {
        uint32_t buf = bufsel[p];
        load_tile(buf,         pq,  qrow0, 768, p * 64, tid);
        load_tile(buf + 16384, pkm, krow0, 768, p * 64, tid);
        load_tile(buf + 32768, pq2, qrow0, 768, p * 64, tid);
        load_tile(buf + 49152, pkv, krow0, 768, p * 64, tid);
        CP_COMMIT();
    }

    for (int c = 0; c < 12; c++) {
        if (c < 11) { CP_WAIT1(); } else { CP_WAIT0(); }
        __syncthreads();
        uint32_t buf = bufsel[c % 3];
        mma_compute_1pass(accM, buf,         buf + 16384, wm, wn, lane);
        mma_compute_1pass(accV, buf + 32768, buf + 49152, wm, wn, lane);
        if (c + 2 < 12) {
            uint32_t lb = bufsel[(c + 2) % 3];
            load_tile(lb,         pq,  qrow0, 768, (c + 2) * 64, tid);
            load_tile(lb + 16384, pkm, krow0, 768, (c + 2) * 64, tid);
            load_tile(lb + 32768, pq2, qrow0, 768, (c + 2) * 64, tid);
            load_tile(lb + 49152, pkv, krow0, 768, (c + 2) * 64, tid);
            CP_COMMIT();
        }
    }

    const float inv_scale = 0.03608439182435161f;  // 1/sqrt(768)
    const float invC = 1.0f / 768.0f;
    float* Sbase = S + (qrow0 * 2048) + (size_t)nt * 128;
#pragma unroll
    for (int mi = 0; mi < 2; mi++) {
#pragma unroll
        for (int ni = 0; ni < 4; ni++) {
            int col = wn * 32 + ni * 8 + (lane & 3) * 2;
            int row0 = wm * 32 + mi * 16 + (lane >> 2);
            float2 v0, v1;
            v0.x = accM[mi][ni][0] * inv_scale - BETA_C * sqrtf(accV[mi][ni][0] * invC);
            v0.y = accM[mi][ni][1] * inv_scale - BETA_C * sqrtf(accV[mi][ni][1] * invC);
            v1.x = accM[mi][ni][2] * inv_scale - BETA_C * sqrtf(accV[mi][ni][2] * invC);
            v1.y = accM[mi][ni][3] * inv_scale - BETA_C * sqrtf(accV[mi][ni][3] * invC);
            *(float2*)(Sbase + (size_t)row0 * 2048 + col)       = v0;
            *(float2*)(Sbase + (size_t)(row0 + 8) * 2048 + col) = v1;
        }
    }
}

// =====================================================================
// Row softmax over 2048 -> attn fp16
// =====================================================================
__global__ __launch_bounds__(256) void softmax_rows(
    const float* __restrict__ S, __half* __restrict__ At)
{
    const size_t row = blockIdx.x;
    const float* r = S + row * 2048;
    const int tid = threadIdx.x;
    __shared__ float sh[8];

    float4 v0 = *(const float4*)(r + tid * 4);
    float4 v1 = *(const float4*)(r + 1024 + tid * 4);

    float mx = fmaxf(fmaxf(fmaxf(v0.x, v0.y), fmaxf(v0.z, v0.w)),
                     fmaxf(fmaxf(v1.x, v1.y), fmaxf(v1.z, v1.w)));
#pragma unroll
    for (int o = 16; o > 0; o >>= 1) mx = fmaxf(mx, __shfl_xor_sync(0xffffffffu, mx, o));
    if ((tid & 31) == 0) sh[tid >> 5] = mx;
    __syncthreads();
    mx = sh[0];
#pragma unroll
    for (int i = 1; i < 8; i++) mx = fmaxf(mx, sh[i]);
    __syncthreads();

    v0.x = expf(v0.x - mx); v0.y = expf(v0.y - mx); v0.z = expf(v0.z - mx); v0.w = expf(v0.w - mx);
    v1.x = expf(v1.x - mx); v1.y = expf(v1.y - mx); v1.z = expf(v1.z - mx); v1.w = expf(v1.w - mx);
    float sum = (v0.x + v0.y + v0.z + v0.w) + (v1.x + v1.y + v1.z + v1.w);
#pragma unroll
    for (int o = 16; o > 0; o >>= 1) sum += __shfl_xor_sync(0xffffffffu, sum, o);
    if ((tid & 31) == 0) sh[tid >> 5] = sum;
    __syncthreads();
    float tot = 0.f;
#pragma unroll
    for (int i = 0; i < 8; i++) tot += sh[i];
    float inv = 1.f / tot;

    size_t i0 = row * 2048 + tid * 4;
    size_t i1 = i0 + 1024;
    *(uint32_t*)(At + i0)     = pack_f16(v0.x * inv, v0.y * inv);
    *(uint32_t*)(At + i0 + 2) = pack_f16(v0.z * inv, v0.w * inv);
    *(uint32_t*)(At + i1)     = pack_f16(v1.x * inv, v1.y * inv);
    *(uint32_t*)(At + i1 + 2) = pack_f16(v1.z * inv, v1.w * inv);
}

// =====================================================================
extern "C" void kernel_launch(void* const* d_in, const int* in_sizes, int n_in,
                              void* d_out, int out_size)
{
    const float* query     = (const float*)d_in[0];
    const float* context   = (const float*)d_in[1];
    const float* eps_noise = (const float*)d_in[2];
    const float* Wq        = (const float*)d_in[3];
    const float* bq        = (const float*)d_in[4];
    const float* Wk        = (const float*)d_in[5];
    const float* bk        = (const float*)d_in[6];
    const float* Wv        = (const float*)d_in[7];
    const float* bv        = (const float*)d_in[8];
    const float* Wo        = (const float*)d_in[9];
    const float* bo        = (const float*)d_in[10];
    const float* ln_k_g    = (const float*)d_in[11];
    const float* ln_k_b    = (const float*)d_in[12];
    const float* ln_v_g    = (const float*)d_in[13];
    const float* ln_v_b    = (const float*)d_in[14];
    const float* gate      = (const float*)d_in[15];
    float* out = (float*)d_out;

    float* pS;
    cudaGetSymbolAddress((void**)&pS, g_S);

    __half *pqf, *pcxf, *pwqf, *pwkf, *pwvf, *pwof;
    __half *pQf, *pQ2f, *pKmu16, *pKvf, *pKmf, *pVmu16, *pVv16, *pVs, *pAt, *pVt, *pOa;
    cudaGetSymbolAddress((void**)&pqf,    g_qf);
    cudaGetSymbolAddress((void**)&pcxf,   g_cxf);
    cudaGetSymbolAddress((void**)&pwqf,   g_wqf);
    cudaGetSymbolAddress((void**)&pwkf,   g_wkf);
    cudaGetSymbolAddress((void**)&pwvf,   g_wvf);
    cudaGetSymbolAddress((void**)&pwof,   g_wof);
    cudaGetSymbolAddress((void**)&pQf,    g_Qf);
    cudaGetSymbolAddress((void**)&pQ2f,   g_Q2f);
    cudaGetSymbolAddress((void**)&pKmu16, g_Kmu16);
    cudaGetSymbolAddress((void**)&pKvf,   g_Kvf);
    cudaGetSymbolAddress((void**)&pKmf,   g_Kmf);
    cudaGetSymbolAddress((void**)&pVmu16, g_Vmu16);
    cudaGetSymbolAddress((void**)&pVv16,  g_Vv16);
    cudaGetSymbolAddress((void**)&pVs,    g_Vs);
    cudaGetSymbolAddress((void**)&pAt,    g_At);
    cudaGetSymbolAddress((void**)&pVt,    g_Vt);
    cudaGetSymbolAddress((void**)&pOa,    g_Oa);

    static int cfg_done = 0;
    if (!cfg_done) {
        cudaFuncSetAttribute(scores_mma, cudaFuncAttributeMaxDynamicSharedMemorySize, SC_SMEM);
        cudaFuncSetAttribute(mma_nt_1p,  cudaFuncAttributeMaxDynamicSharedMemorySize, P1_SMEM);
        cfg_done = 1;
    }

    // 0. operand conversions, single launch (5603328 float4 / 256)
    tohalf_all<<<21888, 256>>>(query, context, Wq, Wk, Wv, Wo);

    // 1. Q projection (mode 4) -> Qf, Q2f fp16
    mma_nt_1p<<<dim3(6, 64), 512, P1_SMEM>>>(pqf, pwqf, 768, 4,
        0, 0, 0, bq, nullptr, pQf, pQ2f, nullptr, nullptr);
    // 2. K projection (mode 0, N=1536) -> Kmu16 fp16 / Kvf fp16
    mma_nt_1p<<<dim3(12, 128), 512, P1_SMEM>>>(pcxf, pwkf, 768, 0,
        0, 0, 0, bk, nullptr, pKmu16, pKvf, nullptr, nullptr);
    // 3. V projection (mode 0, N=1536) -> Vmu16 fp16 / Vv16 fp16
    mma_nt_1p<<<dim3(12, 128), 512, P1_SMEM>>>(pcxf, pwvf, 768, 0,
        0, 0, 0, bv, nullptr, pVmu16, pVv16, nullptr, nullptr);
    // 4. LN + V sampling -> Kmf fp16, Vs fp16
    ln_fuse<<<16384, 256>>>(ln_k_g, ln_k_b, ln_v_g, ln_v_b, eps_noise);
    // 5. transpose V_sample -> Vt fp16 (coalesced)
    transpose_v<<<dim3(64, 24, 8), dim3(32, 8)>>>(pVs, pVt);
    // 6. scores (all 1-pass fp16, dual accumulator, 3-buffer pipeline)
    scores_mma<<<dim3(16, 8, 8), 512, SC_SMEM>>>(pQf, pQ2f, pKmf, pKvf, pS);
    // 7. softmax -> attn fp16
    softmax_rows<<<8192, 256>>>(pS, pAt);
    // 8. attn @ V_sample (mode 2, batched) -> Oa fp16
    mma_nt_1p<<<dim3(6, 8, 8), 512, P1_SMEM>>>(pAt, pVt, 2048, 2,
        (size_t)1024 * 2048, (size_t)768 * 2048, (size_t)1024 * 768,
        nullptr, nullptr, pOa, nullptr, nullptr, nullptr);
    // 9. gated output projection (mode 3)
    mma_nt_1p<<<dim3(6, 64), 512, P1_SMEM>>>(pOa, pwof, 768, 3,
        0, 0, 0, bo, out, nullptr, nullptr, query, gate);
}